// round 16
// baseline (speedup 1.0000x reference)
#include <cuda_runtime.h>
#include <cuda_fp16.h>
#include <cstdint>

#define B_  2
#define S_  2048
#define E_  2048
#define H_  16
#define D_  128
#define M_  (B_ * S_)     // 4096
#define HD  2048

// ---------------------------------------------------------------------------
// Scratch (device globals — allocation-free per harness rules)
// ---------------------------------------------------------------------------
__device__ __half g_xh [(size_t)M_ * E_],  g_xl [(size_t)M_ * E_];   // x split
__device__ __half g_wqh[(size_t)HD * E_],  g_wql[(size_t)HD * E_];   // wq split [n][k]
__device__ __half g_wkh[(size_t)HD * E_],  g_wkl[(size_t)HD * E_];   // wk split
__device__ __half g_wvh[(size_t)HD * E_];                            // wv single
__device__ __half g_woh[(size_t)E_ * HD];                            // wo single
__device__ __half g_qnh[(size_t)M_ * HD],  g_qnl[(size_t)M_ * HD];   // qn split
__device__ __half g_knh[(size_t)M_ * HD],  g_knl[(size_t)M_ * HD];   // kn split
__device__ __half g_vth[(size_t)B_*H_*D_*S_];                        // V^T [z][d][s]
__device__ __half g_aoh[(size_t)M_ * HD];                            // ao single

// ---------------------------------------------------------------------------
// helpers
// ---------------------------------------------------------------------------
__device__ __forceinline__ void cpa16(uint32_t dst, const void* src) {
    asm volatile("cp.async.cg.shared.global [%0], [%1], 16;\n" :: "r"(dst), "l"(src));
}
#define CP_COMMIT() asm volatile("cp.async.commit_group;\n" ::: "memory")
template <int N>
__device__ __forceinline__ void cp_wait() {
    asm volatile("cp.async.wait_group %0;\n" :: "n"(N) : "memory");
}
#define LDMX4(r, a) \
    asm volatile("ldmatrix.sync.aligned.m8n8.x4.shared.b16 {%0,%1,%2,%3}, [%4];" \
        : "=r"((r)[0]), "=r"((r)[1]), "=r"((r)[2]), "=r"((r)[3]) : "r"(a))
#define LDMX2(r, a) \
    asm volatile("ldmatrix.sync.aligned.m8n8.x2.shared.b16 {%0,%1}, [%2];" \
        : "=r"((r)[0]), "=r"((r)[1]) : "r"(a))

__device__ __forceinline__ void mma_f16(float* c, const uint32_t* a, const uint32_t* b) {
    asm("mma.sync.aligned.m16n8k16.row.col.f32.f16.f16.f32 "
        "{%0,%1,%2,%3},{%4,%5,%6,%7},{%8,%9},{%0,%1,%2,%3};"
        : "+f"(c[0]), "+f"(c[1]), "+f"(c[2]), "+f"(c[3])
        : "r"(a[0]), "r"(a[1]), "r"(a[2]), "r"(a[3]), "r"(b[0]), "r"(b[1]));
}

__device__ __forceinline__ void split_h(float x, __half& h, __half& l) {
    h = __float2half_rn(x);
    l = __float2half_rn(x - __half2float(h));
}
__device__ __forceinline__ uint32_t pack2h(__half a, __half b) {
    __half2 v; v.x = a; v.y = b;
    return *(uint32_t*)&v;
}
__device__ __forceinline__ uint32_t sw64(int row, int ch) {
    return (uint32_t)row * 64u + (uint32_t)((ch ^ ((row >> 1) & 3)) << 4);
}
__device__ __forceinline__ uint32_t sw128(int row, int ch) {
    return (uint32_t)row * 128u + (uint32_t)((ch ^ (row & 7)) << 4);
}

// ---------------------------------------------------------------------------
// fp16 1-term GEMM core, BK=64, 3-stage ring, ONE sync per iteration.
// VT=false: fp32 C (ldc 2048). VT=true: transposed fp16 -> dstv[d][s].
// ---------------------------------------------------------------------------
template <bool VT>
__device__ __forceinline__ void gemm_f16_1t(const __half* __restrict__ Ah,
                                            const __half* __restrict__ Bh,
                                            float* __restrict__ C,
                                            __half* __restrict__ dstv,
                                            int s0g, int K)
{
    extern __shared__ char dsm[];
    const uint32_t smem_gen = (uint32_t)__cvta_generic_to_shared(dsm);
    const uint32_t s0 = (smem_gen + 1023) & ~1023u;

    const int tid  = threadIdx.x;
    const int warp = tid >> 5;
    const int lane = tid & 31;
    const int g    = lane >> 2;
    const int t    = lane & 3;
    const int m0w  = (warp & 1) * 64;
    const int n0w  = (warp >> 1) * 32;

    const __half* srcs[2] = {Ah, Bh};

    float acc[4][4][4];
#pragma unroll
    for (int i = 0; i < 4; i++)
#pragma unroll
        for (int j = 0; j < 4; j++)
#pragma unroll
            for (int e = 0; e < 4; e++) acc[i][j][e] = 0.0f;

    const int nch = K >> 6;

    auto issue = [&](int c) {
        const uint32_t stb = s0 + (uint32_t)(c % 3) * 32768u;
        const int kt = c * 64;
#pragma unroll
        for (int arr = 0; arr < 2; arr++) {
            const __half* sp = srcs[arr];
            const uint32_t ab = stb + (uint32_t)arr * 16384u;
#pragma unroll
            for (int j = 0; j < 4; j++) {
                const int loc = tid + j * 256;
                const int row = loc >> 3;
                const int ch  = loc & 7;
                cpa16(ab + sw128(row, ch), sp + (size_t)row * 2048 + kt + ch * 8);
            }
        }
        CP_COMMIT();
    };

    issue(0);
    if (nch > 1) issue(1);

    for (int c = 0; c < nch; c++) {
        if (c + 1 < nch) cp_wait<1>(); else cp_wait<0>();
        __syncthreads();                       // single sync: stage c ready,
        if (c + 2 < nch) issue(c + 2);         // all warps done with stage (c+2)%3

        const uint32_t stb = s0 + (uint32_t)(c % 3) * 32768u;
        const uint32_t aB  = stb;
        const uint32_t bB  = stb + 16384u;

#pragma unroll
        for (int ks = 0; ks < 4; ks++) {
            uint32_t bh[4][2];
#pragma unroll
            for (int nt = 0; nt < 4; nt++) {
                const int rb = n0w + nt * 8 + (lane & 7);
                const int cb = ks * 2 + ((lane >> 3) & 1);
                LDMX2(bh[nt], bB + sw128(rb, cb));
            }
#pragma unroll
            for (int mt = 0; mt < 4; mt++) {
                const int ra = m0w + mt * 16 + (lane & 15);
                const int ca = ks * 2 + (lane >> 4);
                uint32_t ah[4];
                LDMX4(ah, aB + sw128(ra, ca));
#pragma unroll
                for (int nt = 0; nt < 4; nt++)
                    mma_f16(acc[mt][nt], ah, bh[nt]);
            }
        }
    }
    __syncthreads();   // all stage reads done before epilogue SMEM overlay

    if (!VT) {
#pragma unroll
        for (int mt = 0; mt < 4; mt++) {
#pragma unroll
            for (int nt = 0; nt < 4; nt++) {
                const int r0 = m0w + mt * 16 + g;
                const int c0 = n0w + nt * 8 + 2 * t;
                *(float2*)(C + (size_t)r0 * 2048 + c0) =
                    make_float2(acc[mt][nt][0], acc[mt][nt][1]);
                *(float2*)(C + (size_t)(r0 + 8) * 2048 + c0) =
                    make_float2(acc[mt][nt][2], acc[mt][nt][3]);
            }
        }
    } else {
        __half* vt = (__half*)(dsm + (s0 - smem_gen));
#pragma unroll
        for (int mt = 0; mt < 4; mt++) {
#pragma unroll
            for (int nt = 0; nt < 4; nt++) {
                const int r0 = m0w + mt * 16 + g;
                const int c0 = n0w + nt * 8 + 2 * t;
                vt[(c0    ) * 136 + r0    ] = __float2half_rn(acc[mt][nt][0]);
                vt[(c0 + 1) * 136 + r0    ] = __float2half_rn(acc[mt][nt][1]);
                vt[(c0    ) * 136 + r0 + 8] = __float2half_rn(acc[mt][nt][2]);
                vt[(c0 + 1) * 136 + r0 + 8] = __float2half_rn(acc[mt][nt][3]);
            }
        }
        __syncthreads();
#pragma unroll
        for (int j = 0; j < 8; j++) {
            const int vec = tid + j * 256;
            const int d  = vec >> 4;
            const int sc = vec & 15;
            uint4 v;
            v.x = *(uint32_t*)&vt[d * 136 + sc * 8 + 0];
            v.y = *(uint32_t*)&vt[d * 136 + sc * 8 + 2];
            v.z = *(uint32_t*)&vt[d * 136 + sc * 8 + 4];
            v.w = *(uint32_t*)&vt[d * 136 + sc * 8 + 6];
            *(uint4*)(dstv + (size_t)d * S_ + s0g + sc * 8) = v;
        }
    }
}

// ---------------------------------------------------------------------------
// fp16 3-term GEMM, BK=32, 3-stage ring, ONE sync/iter, 2 CTAs/SM. Fused RMS.
// ---------------------------------------------------------------------------
__device__ __forceinline__ void gemm_qk_3t(const __half* __restrict__ Ah,
                                           const __half* __restrict__ Al,
                                           const __half* __restrict__ Bh,
                                           const __half* __restrict__ Bl,
                                           const float* __restrict__ sc,
                                           __half* __restrict__ Oh,
                                           __half* __restrict__ Ol,
                                           size_t obase, int K)
{
    extern __shared__ char dsm[];
    const uint32_t smem_gen = (uint32_t)__cvta_generic_to_shared(dsm);
    const uint32_t s0 = (smem_gen + 1023) & ~1023u;

    const int tid  = threadIdx.x;
    const int warp = tid >> 5;
    const int lane = tid & 31;
    const int g    = lane >> 2;
    const int t    = lane & 3;
    const int m0w  = (warp & 1) * 64;
    const int n0w  = (warp >> 1) * 32;

    const __half* srcs[4] = {Ah, Al, Bh, Bl};

    float acc[4][4][4];
#pragma unroll
    for (int i = 0; i < 4; i++)
#pragma unroll
        for (int j = 0; j < 4; j++)
#pragma unroll
            for (int e = 0; e < 4; e++) acc[i][j][e] = 0.0f;

    const int nch = K >> 5;

    auto issue = [&](int c) {
        const uint32_t stb = s0 + (uint32_t)(c % 3) * 32768u;
        const int kt = c * 32;
#pragma unroll
        for (int j = 0; j < 8; j++) {
            const int loc = tid + j * 256;
            const int arr = loc >> 9;
            const int l2  = loc & 511;
            const int row = l2 >> 2;
            const int ch  = l2 & 3;
            cpa16(stb + (uint32_t)arr * 8192u + sw64(row, ch),
                  srcs[arr] + (size_t)row * 2048 + kt + ch * 8);
        }
        CP_COMMIT();
    };

    issue(0);
    if (nch > 1) issue(1);

    for (int c = 0; c < nch; c++) {
        if (c + 1 < nch) cp_wait<1>(); else cp_wait<0>();
        __syncthreads();
        if (c + 2 < nch) issue(c + 2);

        const uint32_t stb = s0 + (uint32_t)(c % 3) * 32768u;
        const uint32_t aH = stb, aL = stb + 8192u;
        const uint32_t bH = stb + 16384u, bL = stb + 24576u;

#pragma unroll
        for (int ks = 0; ks < 2; ks++) {
            uint32_t bh[4][2], bl[4][2];
#pragma unroll
            for (int nt = 0; nt < 4; nt++) {
                const int rb = n0w + nt * 8 + (lane & 7);
                const int cb = ks * 2 + ((lane >> 3) & 1);
                const uint32_t off = sw64(rb, cb);
                LDMX2(bh[nt], bH + off);
                LDMX2(bl[nt], bL + off);
            }
#pragma unroll
            for (int mt = 0; mt < 4; mt++) {
                const int ra = m0w + mt * 16 + (lane & 15);
                const int ca = ks * 2 + (lane >> 4);
                const uint32_t off = sw64(ra, ca);
                uint32_t ah[4], al[4];
                LDMX4(ah, aH + off);
                LDMX4(al, aL + off);
#pragma unroll
                for (int nt = 0; nt < 4; nt++) mma_f16(acc[mt][nt], ah, bh[nt]);
#pragma unroll
                for (int nt = 0; nt < 4; nt++) mma_f16(acc[mt][nt], ah, bl[nt]);
#pragma unroll
                for (int nt = 0; nt < 4; nt++) mma_f16(acc[mt][nt], al, bh[nt]);
            }
        }
    }
    __syncthreads();   // stage reads done before `part` overlays stage 0

    float* part = (float*)(dsm + (s0 - smem_gen));
    const int ng = warp >> 1;
#pragma unroll
    for (int mt = 0; mt < 4; mt++) {
#pragma unroll
        for (int r = 0; r < 2; r++) {
            float p = 0.0f;
#pragma unroll
            for (int nt = 0; nt < 4; nt++) {
                const float a0 = acc[mt][nt][2*r], a1 = acc[mt][nt][2*r+1];
                p += a0 * a0 + a1 * a1;
            }
            p += __shfl_xor_sync(0xffffffffu, p, 1);
            p += __shfl_xor_sync(0xffffffffu, p, 2);
            if (t == 0)
                part[ng * 128 + m0w + mt * 16 + g + r * 8] = p;
        }
    }
    __syncthreads();

#pragma unroll
    for (int mt = 0; mt < 4; mt++) {
#pragma unroll
        for (int r = 0; r < 2; r++) {
            const int row = m0w + mt * 16 + g + r * 8;
            const float sum = part[row] + part[128 + row]
                            + part[256 + row] + part[384 + row];
            const float rs = rsqrtf(sum * (1.0f / 128.0f) + 1e-6f);
#pragma unroll
            for (int nt = 0; nt < 4; nt++) {
                const int col = n0w + nt * 8 + 2 * t;
                const float2 sv = *(const float2*)(sc + col);
                const float v0 = acc[mt][nt][2*r]   * rs * sv.x;
                const float v1 = acc[mt][nt][2*r+1] * rs * sv.y;
                __half h0, l0, h1, l1;
                split_h(v0, h0, l0); split_h(v1, h1, l1);
                const size_t idx = obase + (size_t)row * 2048 + col;
                *(uint32_t*)(Oh + idx) = pack2h(h0, h1);
                *(uint32_t*)(Ol + idx) = pack2h(l0, l1);
            }
        }
    }
}

__global__ void __launch_bounds__(256, 2) kg_proj(const float* __restrict__ qs,
                                                  const float* __restrict__ ks)
{
    const int z = blockIdx.z;
    const size_t ao = (size_t)blockIdx.y * 128 * 2048;
    const size_t bo = (size_t)blockIdx.x * 128 * 2048;
    const size_t ob = ao + blockIdx.x * 128;
    if (z == 0)
        gemm_qk_3t(g_xh + ao, g_xl + ao, g_wqh + bo, g_wql + bo,
                   qs, g_qnh, g_qnl, ob, E_);
    else if (z == 1)
        gemm_qk_3t(g_xh + ao, g_xl + ao, g_wkh + bo, g_wkl + bo,
                   ks, g_knh, g_knl, ob, E_);
    else {
        const int b  = blockIdx.y >> 4;
        const int zz = b * 16 + blockIdx.x;
        const int s0g = (blockIdx.y & 15) * 128;
        gemm_f16_1t<true>(g_xh + ao, g_wvh + bo, nullptr,
                          g_vth + (size_t)zz * D_ * S_, s0g, E_);
    }
}

__global__ void __launch_bounds__(256, 2) kg_out(float* out)
{
    const size_t ao = (size_t)blockIdx.y * 128 * 2048;
    const size_t bo = (size_t)blockIdx.x * 128 * 2048;
    gemm_f16_1t<false>(g_aoh + ao, g_woh + bo,
                       out + ao + blockIdx.x * 128, nullptr, 0, HD);
}

// ---------------------------------------------------------------------------
// Flash attention: 3-stage K and V rings, ONE sync per iteration.
// S fp16 3-term, PV fp16 1-term.
// SMEM: QH 32K | QL 32K | K: 3 x (KH 16K + KL 16K) | V: 3 x 16K | PH 16K
// ---------------------------------------------------------------------------
#define FL_SMEM 230400

__global__ void __launch_bounds__(256, 1) k_flash()
{
    extern __shared__ char dsm[];
    const uint32_t smem_gen = (uint32_t)__cvta_generic_to_shared(dsm);
    const uint32_t s0 = (smem_gen + 1023) & ~1023u;
    const uint32_t KB0 = s0 + 65536u;
    const uint32_t VB0 = s0 + 163840u;
    const uint32_t PH  = s0 + 212992u;

    const int qt = blockIdx.x, z = blockIdx.y, b = z >> 4, h = z & 15;
    const int tid = threadIdx.x, warp = tid >> 5, lane = tid & 31;
    const int g = lane >> 2, t = lane & 3;

    // ---- Q load (once, joins group 0)
    {
        const __half* qsrc[2] = {g_qnh, g_qnl};
#pragma unroll
        for (int sp = 0; sp < 2; sp++) {
            const uint32_t db = s0 + (uint32_t)sp * 32768u;
#pragma unroll
            for (int j = 0; j < 8; j++) {
                const int i = tid + j * 256;
                const int pl = i >> 10, row = (i >> 3) & 127, ch = i & 7;
                cpa16(db + pl * 16384u + sw128(row, ch),
                      qsrc[sp] + ((size_t)(b * S_ + qt * 128 + row)) * 2048
                               + h * 128 + pl * 64 + ch * 8);
            }
        }
    }

    auto issue_kv = [&](int it) {
        const uint32_t kb = KB0 + (uint32_t)(it % 3) * 32768u;
        const uint32_t vb = VB0 + (uint32_t)(it % 3) * 16384u;
        const int kt = it * 64;
        const __half* ksrc[2] = {g_knh, g_knl};
#pragma unroll
        for (int sp = 0; sp < 2; sp++) {
            const uint32_t kbs = kb + (uint32_t)sp * 16384u;
#pragma unroll
            for (int j = 0; j < 4; j++) {
                const int i = tid + j * 256;
                const int pl = i >> 9, row = (i >> 3) & 63, ch = i & 7;
                cpa16(kbs + pl * 8192u + sw128(row, ch),
                      ksrc[sp] + ((size_t)(b * S_ + kt + row)) * 2048
                               + h * 128 + pl * 64 + ch * 8);
            }
        }
#pragma unroll
        for (int j = 0; j < 4; j++) {
            const int i = tid + j * 256;
            const int row = i >> 3, ch = i & 7;
            cpa16(vb + sw128(row, ch),
                  g_vth + (size_t)z * D_ * S_ + (size_t)row * S_ + kt + ch * 8);
        }
        CP_COMMIT();
    };

    issue_kv(0);
    issue_kv(1);

    float oacc[16][4];
#pragma unroll
    for (int i = 0; i < 16; i++)
#pragma unroll
        for (int e = 0; e < 4; e++) oacc[i][e] = 0.0f;
    float mprev0 = -1e30f, mprev1 = -1e30f, lsum0 = 0.0f, lsum1 = 0.0f;

    for (int it = 0; it < 32; it++) {
        if (it + 1 < 32) cp_wait<1>(); else cp_wait<0>();
        __syncthreads();                     // single sync per iteration
        if (it + 2 < 32) issue_kv(it + 2);   // safe: stage (it+2)%3 last read at it-1

        const uint32_t kb = KB0 + (uint32_t)(it % 3) * 32768u;
        const uint32_t vb = VB0 + (uint32_t)(it % 3) * 16384u;

        float sacc[8][4];
#pragma unroll
        for (int i = 0; i < 8; i++)
#pragma unroll
            for (int e = 0; e < 4; e++) sacc[i][e] = 0.0f;

#pragma unroll
        for (int p = 0; p < 2; p++) {
            const uint32_t qh = s0 + p * 16384u;
            const uint32_t ql = s0 + 32768u + p * 16384u;
            const uint32_t kh = kb + p * 8192u;
            const uint32_t kl = kb + 16384u + p * 8192u;
#pragma unroll
            for (int ks = 0; ks < 4; ks++) {
                const int ra = warp * 16 + (lane & 15);
                const int ca = ks * 2 + (lane >> 4);
                const uint32_t offA = sw128(ra, ca);
                uint32_t ah[4], al[4];
                LDMX4(ah, qh + offA);
                LDMX4(al, ql + offA);
                uint32_t bhe[4][2], bho[4][2], ble[4][2], blo[4][2];
#pragma unroll
                for (int np = 0; np < 4; np++) {
                    const int rb = np * 16 + (lane & 15);
                    const int cb = ks * 2 + (lane >> 4);
                    const uint32_t offB = sw128(rb, cb);
                    uint32_t b4h[4], b4l[4];
                    LDMX4(b4h, kh + offB);
                    LDMX4(b4l, kl + offB);
                    bhe[np][0] = b4h[0]; bhe[np][1] = b4h[2];
                    bho[np][0] = b4h[1]; bho[np][1] = b4h[3];
                    ble[np][0] = b4l[0]; ble[np][1] = b4l[2];
                    blo[np][0] = b4l[1]; blo[np][1] = b4l[3];
                }
#pragma unroll
                for (int np = 0; np < 4; np++) {
                    mma_f16(sacc[2*np],   ah, bhe[np]);
                    mma_f16(sacc[2*np+1], ah, bho[np]);
                }
#pragma unroll
                for (int np = 0; np < 4; np++) {
                    mma_f16(sacc[2*np],   ah, ble[np]);
                    mma_f16(sacc[2*np+1], ah, blo[np]);
                }
#pragma unroll
                for (int np = 0; np < 4; np++) {
                    mma_f16(sacc[2*np],   al, bhe[np]);
                    mma_f16(sacc[2*np+1], al, bho[np]);
                }
            }
        }

        // ---- online softmax
        float mx0 = -1e30f, mx1 = -1e30f;
#pragma unroll
        for (int i = 0; i < 8; i++) {
            mx0 = fmaxf(mx0, fmaxf(sacc[i][0], sacc[i][1]));
            mx1 = fmaxf(mx1, fmaxf(sacc[i][2], sacc[i][3]));
        }
        mx0 = fmaxf(mx0, __shfl_xor_sync(0xffffffffu, mx0, 1));
        mx0 = fmaxf(mx0, __shfl_xor_sync(0xffffffffu, mx0, 2));
        mx1 = fmaxf(mx1, __shfl_xor_sync(0xffffffffu, mx1, 1));
        mx1 = fmaxf(mx1, __shfl_xor_sync(0xffffffffu, mx1, 2));

        const float mn0 = fmaxf(mprev0, mx0);
        const float mn1 = fmaxf(mprev1, mx1);
        const float sc0 = __expf(mprev0 - mn0);
        const float sc1 = __expf(mprev1 - mn1);
        mprev0 = mn0; mprev1 = mn1;

        float su0 = 0.0f, su1 = 0.0f;
#pragma unroll
        for (int i = 0; i < 8; i++) {
            sacc[i][0] = __expf(sacc[i][0] - mn0);
            sacc[i][1] = __expf(sacc[i][1] - mn0);
            sacc[i][2] = __expf(sacc[i][2] - mn1);
            sacc[i][3] = __expf(sacc[i][3] - mn1);
            su0 += sacc[i][0] + sacc[i][1];
            su1 += sacc[i][2] + sacc[i][3];
        }
        su0 += __shfl_xor_sync(0xffffffffu, su0, 1);
        su0 += __shfl_xor_sync(0xffffffffu, su0, 2);
        su1 += __shfl_xor_sync(0xffffffffu, su1, 1);
        su1 += __shfl_xor_sync(0xffffffffu, su1, 2);
        lsum0 = lsum0 * sc0 + su0;
        lsum1 = lsum1 * sc1 + su1;

        if (!__all_sync(0xffffffffu, (sc0 == 1.0f) & (sc1 == 1.0f))) {
#pragma unroll
            for (int i = 0; i < 16; i++) {
                oacc[i][0] *= sc0; oacc[i][1] *= sc0;
                oacc[i][2] *= sc1; oacc[i][3] *= sc1;
            }
        }

        // ---- store P (warp-private rows; only __syncwarp needed)
#pragma unroll
        for (int nt = 0; nt < 8; nt++) {
#pragma unroll
            for (int r = 0; r < 2; r++) {
                const int row = warp * 16 + g + r * 8;
                const uint32_t off = row * 128u + ((nt ^ (row & 7)) << 4) + t * 4u;
                *(uint32_t*)(dsm + (PH + off - smem_gen)) =
                    pack2h(__float2half_rn(sacc[nt][2*r]),
                           __float2half_rn(sacc[nt][2*r+1]));
            }
        }
        __syncwarp();

        // ---- O += P V (1-term)
#pragma unroll
        for (int ks = 0; ks < 4; ks++) {
            const int ra = warp * 16 + (lane & 15);
            const int ca = ks * 2 + (lane >> 4);
            uint32_t ph_[4];
            LDMX4(ph_, PH + sw128(ra, ca));
#pragma unroll
            for (int np = 0; np < 8; np++) {
                const int rb = np * 16 + (lane & 15);
                const int cb = ks * 2 + (lane >> 4);
                uint32_t v4[4];
                LDMX4(v4, vb + sw128(rb, cb));
                uint32_t be[2] = {v4[0], v4[2]};
                uint32_t bo[2] = {v4[1], v4[3]};
                mma_f16(oacc[2*np],   ph_, be);
                mma_f16(oacc[2*np+1], ph_, bo);
            }
        }
        // no trailing sync: 3-stage ring + top sync covers reuse
    }

    // ---- epilogue
    const float inv0 = 1.0f / lsum0, inv1 = 1.0f / lsum1;
    const int row0 = b * S_ + qt * 128 + warp * 16 + g;
#pragma unroll
    for (int nt = 0; nt < 16; nt++) {
        const int col = h * 128 + nt * 8 + 2 * t;
        *(uint32_t*)(g_aoh + (size_t)row0 * 2048 + col) =
            pack2h(__float2half_rn(oacc[nt][0] * inv0),
                   __float2half_rn(oacc[nt][1] * inv0));
        *(uint32_t*)(g_aoh + (size_t)(row0 + 8) * 2048 + col) =
            pack2h(__float2half_rn(oacc[nt][2] * inv1),
                   __float2half_rn(oacc[nt][3] * inv1));
    }
}

// ---------------------------------------------------------------------------
// Prep kernels
// ---------------------------------------------------------------------------
__global__ void k_prep_w(const float* __restrict__ wq, const float* __restrict__ wk,
                         const float* __restrict__ wv, const float* __restrict__ wo)
{
    __shared__ float tbuf[32][33];
    const int z = blockIdx.z;
    const float* src = (z == 0) ? wq : (z == 1) ? wk : (z == 2) ? wv : wo;
    __half* dh = (z == 0) ? g_wqh : (z == 1) ? g_wkh : (z == 2) ? g_wvh : g_woh;
    __half* dl = (z == 0) ? g_wql : (z == 1) ? g_wkl : nullptr;
    const int x0 = blockIdx.x * 32, y0 = blockIdx.y * 32;
    const int tx = threadIdx.x, ty = threadIdx.y;
#pragma unroll
    for (int j = ty; j < 32; j += 8)
        tbuf[j][tx] = src[(size_t)(y0 + j) * 2048 + x0 + tx];
    __syncthreads();
#pragma unroll
    for (int j = ty; j < 32; j += 8) {
        const float v = tbuf[tx][j];
        const size_t idx = (size_t)(x0 + j) * 2048 + y0 + tx;
        if (dl) {
            __half h, l; split_h(v, h, l);
            dh[idx] = h; dl[idx] = l;
        } else {
            dh[idx] = __float2half_rn(v);
        }
    }
}

__global__ void k_prep_x(const float* __restrict__ x)
{
    const size_t i = ((size_t)blockIdx.x * 256 + threadIdx.x) * 4;
    const float4 v = *(const float4*)(x + i);
    __half h[4], l[4];
    split_h(v.x, h[0], l[0]); split_h(v.y, h[1], l[1]);
    split_h(v.z, h[2], l[2]); split_h(v.w, h[3], l[3]);
    *(uint2*)(g_xh + i) = *(uint2*)h;
    *(uint2*)(g_xl + i) = *(uint2*)l;
}

// ---------------------------------------------------------------------------
extern "C" void kernel_launch(void* const* d_in, const int* in_sizes, int n_in,
                              void* d_out, int out_size)
{
    const float* x  = (const float*)d_in[0];
    const float* wq = (const float*)d_in[1];
    const float* wk = (const float*)d_in[2];
    const float* wv = (const float*)d_in[3];
    const float* wo = (const float*)d_in[4];
    const float* qs = (const float*)d_in[5];
    const float* ks = (const float*)d_in[6];
    float* out = (float*)d_out;

    constexpr int SMEMG = 3 * 32768 + 1024;   // 99328 -> 2 CTAs/SM
    cudaFuncSetAttribute(kg_proj, cudaFuncAttributeMaxDynamicSharedMemorySize, SMEMG);
    cudaFuncSetAttribute(kg_out,  cudaFuncAttributeMaxDynamicSharedMemorySize, SMEMG);
    cudaFuncSetAttribute(k_flash, cudaFuncAttributeMaxDynamicSharedMemorySize, FL_SMEM);

    k_prep_w <<<dim3(64, 64, 4), dim3(32, 8)>>>(wq, wk, wv, wo);
    k_prep_x <<<8192, 256>>>(x);
    kg_proj  <<<dim3(16, 32, 3), 256, SMEMG>>>(qs, ks);
    k_flash  <<<dim3(16, 32), 256, FL_SMEM>>>();
    kg_out   <<<dim3(16, 32), 256, SMEMG>>>(out);
}

// round 17
// speedup vs baseline: 1.0196x; 1.0196x over previous
#include <cuda_runtime.h>
#include <cuda_fp16.h>
#include <cstdint>

#define B_  2
#define S_  2048
#define E_  2048
#define H_  16
#define D_  128
#define M_  (B_ * S_)     // 4096
#define HD  2048

// ---------------------------------------------------------------------------
// Scratch (device globals — allocation-free per harness rules)
// ---------------------------------------------------------------------------
__device__ __half g_xh [(size_t)M_ * E_],  g_xl [(size_t)M_ * E_];   // x split
__device__ __half g_wqh[(size_t)HD * E_],  g_wql[(size_t)HD * E_];   // wq split [n][k]
__device__ __half g_wkh[(size_t)HD * E_],  g_wkl[(size_t)HD * E_];   // wk split
__device__ __half g_wvh[(size_t)HD * E_];                            // wv single
__device__ __half g_woh[(size_t)E_ * HD];                            // wo single
__device__ __half g_qnh[(size_t)M_ * HD],  g_qnl[(size_t)M_ * HD];   // qn split
__device__ __half g_knh[(size_t)M_ * HD],  g_knl[(size_t)M_ * HD];   // kn split
__device__ __half g_vth[(size_t)B_*H_*D_*S_];                        // V^T [z][d][s]
__device__ __half g_aoh[(size_t)M_ * HD];                            // ao single

// ---------------------------------------------------------------------------
// helpers
// ---------------------------------------------------------------------------
__device__ __forceinline__ void cpa16(uint32_t dst, const void* src) {
    asm volatile("cp.async.cg.shared.global [%0], [%1], 16;\n" :: "r"(dst), "l"(src));
}
#define CP_COMMIT() asm volatile("cp.async.commit_group;\n" ::: "memory")
template <int N>
__device__ __forceinline__ void cp_wait() {
    asm volatile("cp.async.wait_group %0;\n" :: "n"(N) : "memory");
}
#define LDMX4(r, a) \
    asm volatile("ldmatrix.sync.aligned.m8n8.x4.shared.b16 {%0,%1,%2,%3}, [%4];" \
        : "=r"((r)[0]), "=r"((r)[1]), "=r"((r)[2]), "=r"((r)[3]) : "r"(a))
#define LDMX2(r, a) \
    asm volatile("ldmatrix.sync.aligned.m8n8.x2.shared.b16 {%0,%1}, [%2];" \
        : "=r"((r)[0]), "=r"((r)[1]) : "r"(a))

__device__ __forceinline__ void mma_f16(float* c, const uint32_t* a, const uint32_t* b) {
    asm("mma.sync.aligned.m16n8k16.row.col.f32.f16.f16.f32 "
        "{%0,%1,%2,%3},{%4,%5,%6,%7},{%8,%9},{%0,%1,%2,%3};"
        : "+f"(c[0]), "+f"(c[1]), "+f"(c[2]), "+f"(c[3])
        : "r"(a[0]), "r"(a[1]), "r"(a[2]), "r"(a[3]), "r"(b[0]), "r"(b[1]));
}

__device__ __forceinline__ void split_h(float x, __half& h, __half& l) {
    h = __float2half_rn(x);
    l = __float2half_rn(x - __half2float(h));
}
__device__ __forceinline__ uint32_t pack2h(__half a, __half b) {
    __half2 v; v.x = a; v.y = b;
    return *(uint32_t*)&v;
}
__device__ __forceinline__ uint32_t sw64(int row, int ch) {
    return (uint32_t)row * 64u + (uint32_t)((ch ^ ((row >> 1) & 3)) << 4);
}
__device__ __forceinline__ uint32_t sw128(int row, int ch) {
    return (uint32_t)row * 128u + (uint32_t)((ch ^ (row & 7)) << 4);
}

// ---------------------------------------------------------------------------
// fp16 1-term GEMM core, BK=64, 2-stage (R13 config). VT=false: fp32 C.
// VT=true: transposed fp16 epilogue -> dstv[d][s].
// ---------------------------------------------------------------------------
template <bool VT>
__device__ __forceinline__ void gemm_f16_1t(const __half* __restrict__ Ah,
                                            const __half* __restrict__ Bh,
                                            float* __restrict__ C,
                                            __half* __restrict__ dstv,
                                            int s0g, int K)
{
    extern __shared__ char dsm[];
    const uint32_t smem_gen = (uint32_t)__cvta_generic_to_shared(dsm);
    const uint32_t s0 = (smem_gen + 1023) & ~1023u;

    const int tid  = threadIdx.x;
    const int warp = tid >> 5;
    const int lane = tid & 31;
    const int g    = lane >> 2;
    const int t    = lane & 3;
    const int m0w  = (warp & 1) * 64;
    const int n0w  = (warp >> 1) * 32;

    const __half* srcs[2] = {Ah, Bh};

    float acc[4][4][4];
#pragma unroll
    for (int i = 0; i < 4; i++)
#pragma unroll
        for (int j = 0; j < 4; j++)
#pragma unroll
            for (int e = 0; e < 4; e++) acc[i][j][e] = 0.0f;

    const int nch = K >> 6;

    auto issue = [&](int c) {
        const uint32_t stb = s0 + (uint32_t)(c & 1) * 32768u;
        const int kt = c * 64;
#pragma unroll
        for (int arr = 0; arr < 2; arr++) {
            const __half* sp = srcs[arr];
            const uint32_t ab = stb + (uint32_t)arr * 16384u;
#pragma unroll
            for (int j = 0; j < 4; j++) {
                const int loc = tid + j * 256;
                const int row = loc >> 3;
                const int ch  = loc & 7;
                cpa16(ab + sw128(row, ch), sp + (size_t)row * 2048 + kt + ch * 8);
            }
        }
        CP_COMMIT();
    };

    issue(0);

    for (int c = 0; c < nch; c++) {
        if (c + 1 < nch) { issue(c + 1); cp_wait<1>(); }
        else             { cp_wait<0>(); }
        __syncthreads();

        const uint32_t stb = s0 + (uint32_t)(c & 1) * 32768u;
        const uint32_t aB  = stb;
        const uint32_t bB  = stb + 16384u;

#pragma unroll
        for (int ks = 0; ks < 4; ks++) {
            uint32_t bh[4][2];
#pragma unroll
            for (int nt = 0; nt < 4; nt++) {
                const int rb = n0w + nt * 8 + (lane & 7);
                const int cb = ks * 2 + ((lane >> 3) & 1);
                LDMX2(bh[nt], bB + sw128(rb, cb));
            }
#pragma unroll
            for (int mt = 0; mt < 4; mt++) {
                const int ra = m0w + mt * 16 + (lane & 15);
                const int ca = ks * 2 + (lane >> 4);
                uint32_t ah[4];
                LDMX4(ah, aB + sw128(ra, ca));
#pragma unroll
                for (int nt = 0; nt < 4; nt++)
                    mma_f16(acc[mt][nt], ah, bh[nt]);
            }
        }
        __syncthreads();
    }

    if (!VT) {
#pragma unroll
        for (int mt = 0; mt < 4; mt++) {
#pragma unroll
            for (int nt = 0; nt < 4; nt++) {
                const int r0 = m0w + mt * 16 + g;
                const int c0 = n0w + nt * 8 + 2 * t;
                *(float2*)(C + (size_t)r0 * 2048 + c0) =
                    make_float2(acc[mt][nt][0], acc[mt][nt][1]);
                *(float2*)(C + (size_t)(r0 + 8) * 2048 + c0) =
                    make_float2(acc[mt][nt][2], acc[mt][nt][3]);
            }
        }
    } else {
        __half* vt = (__half*)(dsm + (s0 - smem_gen));
#pragma unroll
        for (int mt = 0; mt < 4; mt++) {
#pragma unroll
            for (int nt = 0; nt < 4; nt++) {
                const int r0 = m0w + mt * 16 + g;
                const int c0 = n0w + nt * 8 + 2 * t;
                vt[(c0    ) * 136 + r0    ] = __float2half_rn(acc[mt][nt][0]);
                vt[(c0 + 1) * 136 + r0    ] = __float2half_rn(acc[mt][nt][1]);
                vt[(c0    ) * 136 + r0 + 8] = __float2half_rn(acc[mt][nt][2]);
                vt[(c0 + 1) * 136 + r0 + 8] = __float2half_rn(acc[mt][nt][3]);
            }
        }
        __syncthreads();
#pragma unroll
        for (int j = 0; j < 8; j++) {
            const int vec = tid + j * 256;
            const int d  = vec >> 4;
            const int sc = vec & 15;
            uint4 v;
            v.x = *(uint32_t*)&vt[d * 136 + sc * 8 + 0];
            v.y = *(uint32_t*)&vt[d * 136 + sc * 8 + 2];
            v.z = *(uint32_t*)&vt[d * 136 + sc * 8 + 4];
            v.w = *(uint32_t*)&vt[d * 136 + sc * 8 + 6];
            *(uint4*)(dstv + (size_t)d * S_ + s0g + sc * 8) = v;
        }
    }
}

// ---------------------------------------------------------------------------
// fp16 3-term GEMM, BK=32, 2-stage, 64KB smem -> 2 CTAs/SM (R13 config).
// ---------------------------------------------------------------------------
__device__ __forceinline__ void gemm_qk_3t(const __half* __restrict__ Ah,
                                           const __half* __restrict__ Al,
                                           const __half* __restrict__ Bh,
                                           const __half* __restrict__ Bl,
                                           const float* __restrict__ sc,
                                           __half* __restrict__ Oh,
                                           __half* __restrict__ Ol,
                                           size_t obase, int K)
{
    extern __shared__ char dsm[];
    const uint32_t smem_gen = (uint32_t)__cvta_generic_to_shared(dsm);
    const uint32_t s0 = (smem_gen + 1023) & ~1023u;

    const int tid  = threadIdx.x;
    const int warp = tid >> 5;
    const int lane = tid & 31;
    const int g    = lane >> 2;
    const int t    = lane & 3;
    const int m0w  = (warp & 1) * 64;
    const int n0w  = (warp >> 1) * 32;

    const __half* srcs[4] = {Ah, Al, Bh, Bl};

    float acc[4][4][4];
#pragma unroll
    for (int i = 0; i < 4; i++)
#pragma unroll
        for (int j = 0; j < 4; j++)
#pragma unroll
            for (int e = 0; e < 4; e++) acc[i][j][e] = 0.0f;

    const int nch = K >> 5;

    auto issue = [&](int c) {
        const uint32_t stb = s0 + (uint32_t)(c & 1) * 32768u;
        const int kt = c * 32;
#pragma unroll
        for (int j = 0; j < 8; j++) {
            const int loc = tid + j * 256;
            const int arr = loc >> 9;
            const int l2  = loc & 511;
            const int row = l2 >> 2;
            const int ch  = l2 & 3;
            cpa16(stb + (uint32_t)arr * 8192u + sw64(row, ch),
                  srcs[arr] + (size_t)row * 2048 + kt + ch * 8);
        }
        CP_COMMIT();
    };

    issue(0);

    for (int c = 0; c < nch; c++) {
        if (c + 1 < nch) { issue(c + 1); cp_wait<1>(); }
        else             { cp_wait<0>(); }
        __syncthreads();

        const uint32_t stb = s0 + (uint32_t)(c & 1) * 32768u;
        const uint32_t aH = stb, aL = stb + 8192u;
        const uint32_t bH = stb + 16384u, bL = stb + 24576u;

#pragma unroll
        for (int ks = 0; ks < 2; ks++) {
            uint32_t bh[4][2], bl[4][2];
#pragma unroll
            for (int nt = 0; nt < 4; nt++) {
                const int rb = n0w + nt * 8 + (lane & 7);
                const int cb = ks * 2 + ((lane >> 3) & 1);
                const uint32_t off = sw64(rb, cb);
                LDMX2(bh[nt], bH + off);
                LDMX2(bl[nt], bL + off);
            }
#pragma unroll
            for (int mt = 0; mt < 4; mt++) {
                const int ra = m0w + mt * 16 + (lane & 15);
                const int ca = ks * 2 + (lane >> 4);
                const uint32_t off = sw64(ra, ca);
                uint32_t ah[4], al[4];
                LDMX4(ah, aH + off);
                LDMX4(al, aL + off);
#pragma unroll
                for (int nt = 0; nt < 4; nt++) mma_f16(acc[mt][nt], ah, bh[nt]);
#pragma unroll
                for (int nt = 0; nt < 4; nt++) mma_f16(acc[mt][nt], ah, bl[nt]);
#pragma unroll
                for (int nt = 0; nt < 4; nt++) mma_f16(acc[mt][nt], al, bh[nt]);
            }
        }
        __syncthreads();
    }

    float* part = (float*)(dsm + (s0 - smem_gen));
    const int ng = warp >> 1;
#pragma unroll
    for (int mt = 0; mt < 4; mt++) {
#pragma unroll
        for (int r = 0; r < 2; r++) {
            float p = 0.0f;
#pragma unroll
            for (int nt = 0; nt < 4; nt++) {
                const float a0 = acc[mt][nt][2*r], a1 = acc[mt][nt][2*r+1];
                p += a0 * a0 + a1 * a1;
            }
            p += __shfl_xor_sync(0xffffffffu, p, 1);
            p += __shfl_xor_sync(0xffffffffu, p, 2);
            if (t == 0)
                part[ng * 128 + m0w + mt * 16 + g + r * 8] = p;
        }
    }
    __syncthreads();

#pragma unroll
    for (int mt = 0; mt < 4; mt++) {
#pragma unroll
        for (int r = 0; r < 2; r++) {
            const int row = m0w + mt * 16 + g + r * 8;
            const float sum = part[row] + part[128 + row]
                            + part[256 + row] + part[384 + row];
            const float rs = rsqrtf(sum * (1.0f / 128.0f) + 1e-6f);
#pragma unroll
            for (int nt = 0; nt < 4; nt++) {
                const int col = n0w + nt * 8 + 2 * t;
                const float2 sv = *(const float2*)(sc + col);
                const float v0 = acc[mt][nt][2*r]   * rs * sv.x;
                const float v1 = acc[mt][nt][2*r+1] * rs * sv.y;
                __half h0, l0, h1, l1;
                split_h(v0, h0, l0); split_h(v1, h1, l1);
                const size_t idx = obase + (size_t)row * 2048 + col;
                *(uint32_t*)(Oh + idx) = pack2h(h0, h1);
                *(uint32_t*)(Ol + idx) = pack2h(l0, l1);
            }
        }
    }
}

__global__ void __launch_bounds__(256, 2) kg_proj(const float* __restrict__ qs,
                                                  const float* __restrict__ ks)
{
    const int z = blockIdx.z;
    const size_t ao = (size_t)blockIdx.y * 128 * 2048;
    const size_t bo = (size_t)blockIdx.x * 128 * 2048;
    const size_t ob = ao + blockIdx.x * 128;
    if (z == 0)
        gemm_qk_3t(g_xh + ao, g_xl + ao, g_wqh + bo, g_wql + bo,
                   qs, g_qnh, g_qnl, ob, E_);
    else if (z == 1)
        gemm_qk_3t(g_xh + ao, g_xl + ao, g_wkh + bo, g_wkl + bo,
                   ks, g_knh, g_knl, ob, E_);
    else {
        const int b  = blockIdx.y >> 4;
        const int zz = b * 16 + blockIdx.x;
        const int s0g = (blockIdx.y & 15) * 128;
        gemm_f16_1t<true>(g_xh + ao, g_wvh + bo, nullptr,
                          g_vth + (size_t)zz * D_ * S_, s0g, E_);
    }
}

__global__ void __launch_bounds__(256, 2) kg_out(float* out)
{
    const size_t ao = (size_t)blockIdx.y * 128 * 2048;
    const size_t bo = (size_t)blockIdx.x * 128 * 2048;
    gemm_f16_1t<false>(g_aoh + ao, g_woh + bo,
                       out + ao + blockIdx.x * 128, nullptr, 0, HD);
}

// ---------------------------------------------------------------------------
// Flash attention: 128 threads / 4 warps, q-tile 64, key-tile 32,
// 2-stage K/V ring, ~85KB SMEM -> 2 CTAs/SM (cross-CTA overlap).
// S fp16 3-term, PV fp16 1-term. Warp w owns q-rows [w*16, w*16+16).
// SMEM: QH 16K | QL 16K | 2 st x (KH 8K | KL 8K | V 8K) | PH 4K
// ---------------------------------------------------------------------------
#define FL_SMEM 87040

__global__ void __launch_bounds__(128, 2) k_flash()
{
    extern __shared__ char dsm[];
    const uint32_t smem_gen = (uint32_t)__cvta_generic_to_shared(dsm);
    const uint32_t s0 = (smem_gen + 1023) & ~1023u;
    const uint32_t ST0 = s0 + 32768u;            // stages
    const uint32_t PH  = s0 + 81920u;

    const int qt = blockIdx.x, z = blockIdx.y, b = z >> 4, h = z & 15;
    const int tid = threadIdx.x, warp = tid >> 5, lane = tid & 31;
    const int g = lane >> 2, t = lane & 3;

    // ---- Q load (once): 64 rows x 128 d, hi/lo, 2 planes
    {
        const __half* qsrc[2] = {g_qnh, g_qnl};
#pragma unroll
        for (int sp = 0; sp < 2; sp++) {
            const uint32_t db = s0 + (uint32_t)sp * 16384u;
#pragma unroll
            for (int j = 0; j < 8; j++) {
                const int i = tid + j * 128;          // 0..1023
                const int pl = i >> 9, row = (i >> 3) & 63, ch = i & 7;
                cpa16(db + pl * 8192u + sw128(row, ch),
                      qsrc[sp] + ((size_t)(b * S_ + qt * 64 + row)) * 2048
                               + h * 128 + pl * 64 + ch * 8);
            }
        }
    }

    auto issue_kv = [&](int it) {
        const uint32_t stb = ST0 + (uint32_t)(it & 1) * 24576u;
        const int kt = it * 32;
        const __half* ksrc[2] = {g_knh, g_knl};
        // K hi/lo: 2 splits x 2 planes x 32 rows x 8 chunks = 1024
#pragma unroll
        for (int j = 0; j < 8; j++) {
            const int i = tid + j * 128;
            const int sp = i >> 9;
            const int l  = i & 511;
            const int pl = l >> 8, row = (l >> 3) & 31, ch = l & 7;
            cpa16(stb + (uint32_t)sp * 8192u + pl * 4096u + sw128(row, ch),
                  ksrc[sp] + ((size_t)(b * S_ + kt + row)) * 2048
                           + h * 128 + pl * 64 + ch * 8);
        }
        // V^T: 128 d-rows x 4 chunks (64B rows) = 512
#pragma unroll
        for (int j = 0; j < 4; j++) {
            const int i = tid + j * 128;
            const int row = i >> 2, ch = i & 3;
            cpa16(stb + 16384u + sw64(row, ch),
                  g_vth + (size_t)z * D_ * S_ + (size_t)row * S_ + kt + ch * 8);
        }
        CP_COMMIT();
    };

    issue_kv(0);

    float oacc[16][4];
#pragma unroll
    for (int i = 0; i < 16; i++)
#pragma unroll
        for (int e = 0; e < 4; e++) oacc[i][e] = 0.0f;
    float mprev0 = -1e30f, mprev1 = -1e30f, lsum0 = 0.0f, lsum1 = 0.0f;

    for (int it = 0; it < 64; it++) {
        if (it + 1 < 64) { issue_kv(it + 1); cp_wait<1>(); }
        else             { cp_wait<0>(); }
        __syncthreads();

        const uint32_t stb = ST0 + (uint32_t)(it & 1) * 24576u;

        // ---- S = (Qh+Ql)(Kh+Kl)^T 3-term: 16 q-rows x 32 keys per warp
        float sacc[4][4];
#pragma unroll
        for (int i = 0; i < 4; i++)
#pragma unroll
            for (int e = 0; e < 4; e++) sacc[i][e] = 0.0f;

#pragma unroll
        for (int p = 0; p < 2; p++) {
            const uint32_t qh = s0 + p * 8192u;
            const uint32_t ql = s0 + 16384u + p * 8192u;
            const uint32_t kh = stb + p * 4096u;
            const uint32_t kl = stb + 8192u + p * 4096u;
#pragma unroll
            for (int ks = 0; ks < 4; ks++) {
                const int ra = warp * 16 + (lane & 15);
                const int ca = ks * 2 + (lane >> 4);
                const uint32_t offA = sw128(ra, ca);
                uint32_t ah[4], al[4];
                LDMX4(ah, qh + offA);
                LDMX4(al, ql + offA);
#pragma unroll
                for (int np = 0; np < 2; np++) {
                    const int rb = np * 16 + (lane & 15);
                    const uint32_t offB = sw128(rb, ca);
                    uint32_t b4h[4], b4l[4];
                    LDMX4(b4h, kh + offB);
                    LDMX4(b4l, kl + offB);
                    uint32_t be[2] = {b4h[0], b4h[2]};
                    uint32_t bo[2] = {b4h[1], b4h[3]};
                    uint32_t le[2] = {b4l[0], b4l[2]};
                    uint32_t lo[2] = {b4l[1], b4l[3]};
                    mma_f16(sacc[2*np],   ah, be);
                    mma_f16(sacc[2*np],   ah, le);
                    mma_f16(sacc[2*np],   al, be);
                    mma_f16(sacc[2*np+1], ah, bo);
                    mma_f16(sacc[2*np+1], ah, lo);
                    mma_f16(sacc[2*np+1], al, bo);
                }
            }
        }

        // ---- online softmax (rows g and g+8)
        float mx0 = -1e30f, mx1 = -1e30f;
#pragma unroll
        for (int i = 0; i < 4; i++) {
            mx0 = fmaxf(mx0, fmaxf(sacc[i][0], sacc[i][1]));
            mx1 = fmaxf(mx1, fmaxf(sacc[i][2], sacc[i][3]));
        }
        mx0 = fmaxf(mx0, __shfl_xor_sync(0xffffffffu, mx0, 1));
        mx0 = fmaxf(mx0, __shfl_xor_sync(0xffffffffu, mx0, 2));
        mx1 = fmaxf(mx1, __shfl_xor_sync(0xffffffffu, mx1, 1));
        mx1 = fmaxf(mx1, __shfl_xor_sync(0xffffffffu, mx1, 2));

        const float mn0 = fmaxf(mprev0, mx0);
        const float mn1 = fmaxf(mprev1, mx1);
        const float sc0 = __expf(mprev0 - mn0);
        const float sc1 = __expf(mprev1 - mn1);
        mprev0 = mn0; mprev1 = mn1;

        float su0 = 0.0f, su1 = 0.0f;
#pragma unroll
        for (int i = 0; i < 4; i++) {
            sacc[i][0] = __expf(sacc[i][0] - mn0);
            sacc[i][1] = __expf(sacc[i][1] - mn0);
            sacc[i][2] = __expf(sacc[i][2] - mn1);
            sacc[i][3] = __expf(sacc[i][3] - mn1);
            su0 += sacc[i][0] + sacc[i][1];
            su1 += sacc[i][2] + sacc[i][3];
        }
        su0 += __shfl_xor_sync(0xffffffffu, su0, 1);
        su0 += __shfl_xor_sync(0xffffffffu, su0, 2);
        su1 += __shfl_xor_sync(0xffffffffu, su1, 1);
        su1 += __shfl_xor_sync(0xffffffffu, su1, 2);
        lsum0 = lsum0 * sc0 + su0;
        lsum1 = lsum1 * sc1 + su1;

        if (!__all_sync(0xffffffffu, (sc0 == 1.0f) & (sc1 == 1.0f))) {
#pragma unroll
            for (int i = 0; i < 16; i++) {
                oacc[i][0] *= sc0; oacc[i][1] *= sc0;
                oacc[i][2] *= sc1; oacc[i][3] *= sc1;
            }
        }

        // ---- store P (single fp16), 64B rows, warp-private
#pragma unroll
        for (int nt = 0; nt < 4; nt++) {
#pragma unroll
            for (int r = 0; r < 2; r++) {
                const int row = warp * 16 + g + r * 8;
                const uint32_t off = sw64(row, nt) + t * 4u;
                *(uint32_t*)(dsm + (PH + off - smem_gen)) =
                    pack2h(__float2half_rn(sacc[nt][2*r]),
                           __float2half_rn(sacc[nt][2*r+1]));
            }
        }
        __syncwarp();

        // ---- O += P V (1-term): 16 q-rows x 128 d, k = 32 keys
        const uint32_t vb = stb + 16384u;
#pragma unroll
        for (int ks = 0; ks < 2; ks++) {
            const int ra = warp * 16 + (lane & 15);
            const int ca = ks * 2 + (lane >> 4);
            uint32_t ph_[4];
            LDMX4(ph_, PH + sw64(ra, ca));
#pragma unroll
            for (int np = 0; np < 8; np++) {
                const int rb = np * 16 + (lane & 15);
                uint32_t v4[4];
                LDMX4(v4, vb + sw64(rb, ca));
                uint32_t be[2] = {v4[0], v4[2]};
                uint32_t bo[2] = {v4[1], v4[3]};
                mma_f16(oacc[2*np],   ph_, be);
                mma_f16(oacc[2*np+1], ph_, bo);
            }
        }
        __syncthreads();   // protect stage + P before next iteration
    }

    // ---- epilogue: O / l -> single fp16
    const float inv0 = 1.0f / lsum0, inv1 = 1.0f / lsum1;
    const int row0 = b * S_ + qt * 64 + warp * 16 + g;
#pragma unroll
    for (int nt = 0; nt < 16; nt++) {
        const int col = h * 128 + nt * 8 + 2 * t;
        *(uint32_t*)(g_aoh + (size_t)row0 * 2048 + col) =
            pack2h(__float2half_rn(oacc[nt][0] * inv0),
                   __float2half_rn(oacc[nt][1] * inv0));
        *(uint32_t*)(g_aoh + (size_t)(row0 + 8) * 2048 + col) =
            pack2h(__float2half_rn(oacc[nt][2] * inv1),
                   __float2half_rn(oacc[nt][3] * inv1));
    }
}

// ---------------------------------------------------------------------------
// Prep kernels
// ---------------------------------------------------------------------------
__global__ void k_prep_w(const float* __restrict__ wq, const float* __restrict__ wk,
                         const float* __restrict__ wv, const float* __restrict__ wo)
{
    __shared__ float tbuf[32][33];
    const int z = blockIdx.z;
    const float* src = (z == 0) ? wq : (z == 1) ? wk : (z == 2) ? wv : wo;
    __half* dh = (z == 0) ? g_wqh : (z == 1) ? g_wkh : (z == 2) ? g_wvh : g_woh;
    __half* dl = (z == 0) ? g_wql : (z == 1) ? g_wkl : nullptr;
    const int x0 = blockIdx.x * 32, y0 = blockIdx.y * 32;
    const int tx = threadIdx.x, ty = threadIdx.y;
#pragma unroll
    for (int j = ty; j < 32; j += 8)
        tbuf[j][tx] = src[(size_t)(y0 + j) * 2048 + x0 + tx];
    __syncthreads();
#pragma unroll
    for (int j = ty; j < 32; j += 8) {
        const float v = tbuf[tx][j];
        const size_t idx = (size_t)(x0 + j) * 2048 + y0 + tx;
        if (dl) {
            __half h, l; split_h(v, h, l);
            dh[idx] = h; dl[idx] = l;
        } else {
            dh[idx] = __float2half_rn(v);
        }
    }
}

__global__ void k_prep_x(const float* __restrict__ x)
{
    const size_t i = ((size_t)blockIdx.x * 256 + threadIdx.x) * 4;
    const float4 v = *(const float4*)(x + i);
    __half h[4], l[4];
    split_h(v.x, h[0], l[0]); split_h(v.y, h[1], l[1]);
    split_h(v.z, h[2], l[2]); split_h(v.w, h[3], l[3]);
    *(uint2*)(g_xh + i) = *(uint2*)h;
    *(uint2*)(g_xl + i) = *(uint2*)l;
}

// ---------------------------------------------------------------------------
extern "C" void kernel_launch(void* const* d_in, const int* in_sizes, int n_in,
                              void* d_out, int out_size)
{
    const float* x  = (const float*)d_in[0];
    const float* wq = (const float*)d_in[1];
    const float* wk = (const float*)d_in[2];
    const float* wv = (const float*)d_in[3];
    const float* wo = (const float*)d_in[4];
    const float* qs = (const float*)d_in[5];
    const float* ks = (const float*)d_in[6];
    float* out = (float*)d_out;

    constexpr int SMEMG = 2 * 32768 + 1024;
    cudaFuncSetAttribute(kg_proj, cudaFuncAttributeMaxDynamicSharedMemorySize, SMEMG);
    cudaFuncSetAttribute(kg_out,  cudaFuncAttributeMaxDynamicSharedMemorySize, SMEMG);
    cudaFuncSetAttribute(k_flash, cudaFuncAttributeMaxDynamicSharedMemorySize, FL_SMEM);

    k_prep_w <<<dim3(64, 64, 4), dim3(32, 8)>>>(wq, wk, wv, wo);
    k_prep_x <<<8192, 256>>>(x);
    kg_proj  <<<dim3(16, 32, 3), 256, SMEMG>>>(qs, ks);
    k_flash  <<<dim3(32, 32), 128, FL_SMEM>>>();
    kg_out   <<<dim3(16, 32), 256, SMEMG>>>(out);
}